// round 10
// baseline (speedup 1.0000x reference)
#include <cuda_runtime.h>

// HGT_DNF conjunction layer — all-FMA formulation.
// idx structure: pairs {r, 53+r}, weight row 53 unused. RR=53.
// out[b,o] = sum_r( A*w - dU*|w| ) + max_r( dV*|w| )
// max path via p-norm (P=32):
//   max_r dV_r*|w_ro| ≈ s_b * t_o * ( sum_r Vp[b,r]*awp[r,o] )^(1/32)
//   s_b = max_r dV[b,r],  t_o = max_r |w[r,o]|
//   Vp = (dV/s_b)^32,  awp = (|w|/t_o)^32      (ratios <= 1; subnormal-safe)
// Inner loop = 3 packed FFMA2 chains. Epilogue = 2 MUFU per element.

#define BB 4096
#define NPRED 106
#define RR 53
#define OO 1024
#define DELTA_C 0.01f

#define TB 128
#define TO 64
#define THREADS 256
#define BTILES_PER_CTA 2

__device__ float g_A[RR * BB];
__device__ float g_nU[RR * BB];   // -DELTA*sum|x|
__device__ float g_Vp[RR * BB];   // (max|x| ratio)^32
__device__ float g_s[BB];         // DELTA*max_r max|x|

// ---- packed f32x2 helpers (Blackwell; only reachable via PTX) ----
#define FMA2(d, a, b, c) \
    asm("fma.rn.f32x2 %0, %1, %2, %3;" : "=l"(d) : "l"(a), "l"(b), "l"(c))
#define PACK2(d, lo, hi) \
    asm("mov.b64 %0, {%1, %2};" : "=l"(d) : "f"(lo), "f"(hi))
#define UNPACK2(lo, hi, v) \
    asm("mov.b64 {%0, %1}, %2;" : "=f"(lo), "=f"(hi) : "l"(v))
#define ABS2(d, a) \
    asm("and.b64 %0, %1, 0x7FFFFFFF7FFFFFFF;" : "=l"(d) : "l"(a))

// MUFU lg2 / ex2 via PTX (device-safe fast approximations)
__device__ __forceinline__ float lg2f(float v) {
    float r;
    asm("lg2.approx.f32 %0, %1;" : "=f"(r) : "f"(v));
    return r;
}
__device__ __forceinline__ float ex2f(float v) {
    float r;
    asm("ex2.approx.f32 %0, %1;" : "=f"(r) : "f"(v));
    return r;
}

__device__ __forceinline__ float pow32f(float v) {
    v = v * v;   // ^2
    v = v * v;   // ^4
    v = v * v;   // ^8
    v = v * v;   // ^16
    return v * v;  // ^32
}

// ---------------- Kernel 1: per-batch-row pair aggregation ----------------
#define ROWS_PB 128
#define XPAD 107
__global__ void __launch_bounds__(128) k_rows(const float* __restrict__ x) {
    __shared__ float s_x[ROWS_PB * XPAD];
    int tid = threadIdx.x;
    int b0 = blockIdx.x * ROWS_PB;

    for (int i = tid; i < ROWS_PB * NPRED; i += 128) {
        int row = i / NPRED, col = i % NPRED;
        s_x[row * XPAD + col] = x[(long)(b0 + row) * NPRED + col];
    }
    __syncthreads();

    const float* xr = &s_x[tid * XPAD];
    int b = b0 + tid;

    float mx = 0.0f;
#pragma unroll 4
    for (int r = 0; r < RR; r++) {
        float x1 = xr[r];
        float x2 = xr[53 + r];
        float A = ((x1 >= -1.0f) ? x1 : 0.0f) + ((x2 >= -1.0f) ? x2 : 0.0f);
        float a1 = fabsf(x1), a2 = fabsf(x2);
        g_A [r * BB + b] = A;
        g_nU[r * BB + b] = -DELTA_C * (a1 + a2);
        mx = fmaxf(mx, fmaxf(a1, a2));
    }
    float inv = (mx > 0.0f) ? (1.0f / mx) : 0.0f;
#pragma unroll 4
    for (int r = 0; r < RR; r++) {
        float dv = fmaxf(fabsf(xr[r]), fabsf(xr[53 + r]));
        g_Vp[r * BB + b] = pow32f(dv * inv);
    }
    g_s[b] = DELTA_C * mx;
}

// ---------------- Kernel 2: fused triple-FMA2 GEMM ----------------
// grid = (16, 16) = 256 CTAs, single wave at 2 CTAs/SM. Weight-side smem
// (w, awp, t) staged once; CTA loops over 2 batch tiles of 128 rows.
// 256 threads, 8x4 micro-tile (4 f32x2 row-pairs x 4 cols).
__global__ void __launch_bounds__(THREADS, 2)
k_main(const float* __restrict__ w, float* __restrict__ out) {
    extern __shared__ float sm[];
    float* sA   = sm;                  // [RR][TB]
    float* sU   = sA   + RR * TB;
    float* sVp  = sU   + RR * TB;
    float* sW   = sVp  + RR * TB;      // [RR][TO]
    float* sAwp = sW   + RR * TO;      // [RR][TO]
    float* sT   = sAwp + RR * TO;      // [TO] col maxes
    float* sTi  = sT   + TO;           // [TO] 1/max
    float* sS   = sTi  + TO;           // [TB] row scales

    int tid = threadIdx.x;
    int o0 = blockIdx.x * TO;

    // Stage weight tile.
    for (int i = tid; i < RR * TO; i += THREADS) {
        int r = i >> 6, o = i & 63;
        sW[i] = __ldg(&w[r * OO + o0 + o]);
    }
    __syncthreads();
    // Column maxes t_o.
    if (tid < TO) {
        float m = 0.0f;
        for (int r = 0; r < RR; r++) m = fmaxf(m, fabsf(sW[r * TO + tid]));
        sT[tid] = m;
        sTi[tid] = (m > 0.0f) ? (1.0f / m) : 0.0f;
    }
    __syncthreads();
    // awp = (|w|/t)^32.
    for (int i = tid; i < RR * TO; i += THREADS) {
        int o = i & 63;
        sAwp[i] = pow32f(fabsf(sW[i]) * sTi[o]);
    }

    int tx = tid & 15;          // col group -> 4 cols
    int ty = tid >> 4;          // row group -> 8 rows (4 packed pairs)
    int ro = ty * 8;
    int co = tx * 4;

    for (int j = 0; j < BTILES_PER_CTA; j++) {
        int b0 = (blockIdx.y * BTILES_PER_CTA + j) * TB;

        for (int i = tid; i < RR * TB; i += THREADS) {
            int r = i >> 7, b = i & 127;
            int g = r * BB + b0 + b;
            sA[i]  = g_A[g];
            sU[i]  = g_nU[g];
            sVp[i] = g_Vp[g];
        }
        if (tid < TB) sS[tid] = g_s[b0 + tid];
        __syncthreads();

        unsigned long long acc[4][4];   // packed sum accumulators
        unsigned long long pn[4][4];    // packed p-norm accumulators
#pragma unroll
        for (int p = 0; p < 4; p++)
#pragma unroll
            for (int c = 0; c < 4; c++) { acc[p][c] = 0ULL; pn[p][c] = 0ULL; }

#pragma unroll 4
        for (int r = 0; r < RR; r++) {
            ulonglong2 Av0 = *(const ulonglong2*)&sA [r * TB + ro];
            ulonglong2 Av1 = *(const ulonglong2*)&sA [r * TB + ro + 4];
            ulonglong2 Uv0 = *(const ulonglong2*)&sU [r * TB + ro];
            ulonglong2 Uv1 = *(const ulonglong2*)&sU [r * TB + ro + 4];
            ulonglong2 Vv0 = *(const ulonglong2*)&sVp[r * TB + ro];
            ulonglong2 Vv1 = *(const ulonglong2*)&sVp[r * TB + ro + 4];
            unsigned long long Ap[4] = {Av0.x, Av0.y, Av1.x, Av1.y};
            unsigned long long Up[4] = {Uv0.x, Uv0.y, Uv1.x, Uv1.y};
            unsigned long long Vp[4] = {Vv0.x, Vv0.y, Vv1.x, Vv1.y};

            float4 wv4 = *(const float4*)&sW  [r * TO + co];
            float4 pv4 = *(const float4*)&sAwp[r * TO + co];
            float wv[4] = {wv4.x, wv4.y, wv4.z, wv4.w};
            float pv[4] = {pv4.x, pv4.y, pv4.z, pv4.w};
            unsigned long long wd[4], ad[4], pd[4];
#pragma unroll
            for (int c = 0; c < 4; c++) {
                PACK2(wd[c], wv[c], wv[c]);
                ABS2(ad[c], wd[c]);
                PACK2(pd[c], pv[c], pv[c]);
            }

#pragma unroll
            for (int p = 0; p < 4; p++) {
#pragma unroll
                for (int c = 0; c < 4; c++) {
                    FMA2(acc[p][c], Ap[p], wd[c], acc[p][c]);   // + A*w
                    FMA2(acc[p][c], Up[p], ad[c], acc[p][c]);   // - dU*|w|
                    FMA2(pn [p][c], Vp[p], pd[c], pn [p][c]);   // p-norm sum
                }
            }
        }

        // Epilogue: out = acc + s_b * t_o * S^(1/32)
#pragma unroll
        for (int i = 0; i < 8; i++) {
            int p = i >> 1;
            float srow = sS[ro + i];
            float4 res;
            float a[4];
#pragma unroll
            for (int c = 0; c < 4; c++) {
                float alo, ahi, slo, shi;
                UNPACK2(alo, ahi, acc[p][c]);
                UNPACK2(slo, shi, pn[p][c]);
                float S = (i & 1) ? shi : slo;
                float base = (i & 1) ? ahi : alo;
                float root = ex2f(lg2f(S) * 0.03125f);  // S^(1/32); S=0 -> 0
                a[c] = base + srow * sT[co + c] * root;
            }
            res.x = a[0]; res.y = a[1]; res.z = a[2]; res.w = a[3];
            *(float4*)&out[(long)(b0 + ro + i) * OO + o0 + co] = res;
        }
        __syncthreads();   // row arrays reused next j
    }
}

extern "C" void kernel_launch(void* const* d_in, const int* in_sizes, int n_in,
                              void* d_out, int out_size) {
    const float* x = (const float*)d_in[0];   // [4096, 106] f32
    const float* w = (const float*)d_in[1];   // [54, 1024] f32 (row 53 unused)
    float* out = (float*)d_out;               // [4096, 1024] f32

    const int smem = (3 * RR * TB + 2 * RR * TO + 2 * TO + TB) * (int)sizeof(float);
    cudaFuncSetAttribute(k_main, cudaFuncAttributeMaxDynamicSharedMemorySize, smem);

    k_rows<<<BB / ROWS_PB, 128>>>(x);
    dim3 grid(OO / TO, BB / (TB * BTILES_PER_CTA));   // (16, 16)
    k_main<<<grid, THREADS, smem>>>(w, out);
}

// round 12
// speedup vs baseline: 1.0314x; 1.0314x over previous
#include <cuda_runtime.h>
#include <cuda_bf16.h>
#include <cstdint>

// HGT_DNF conjunction layer via portable tensor-core MMA (mma.sync bf16).
// idx structure: pairs {r, 53+r}, weight row 53 unused. RR=53.
//   out[b,o] = sum_r( A*w - dU*|w| ) + max_r( dV*|w| )
// max via p-norm P=32:  s_b * t_o * ( sum_r Vp*awp )^(1/32)
// Two GEMMs over expanded K=384 (6x64 bf16):
//   k in [0,318): split-bf16 sum path (hi*hi + hi*lo + lo*hi), -> D1
//   k in [320,373): p-norm path (single bf16)                  -> D2
// k16-step g: g<20 -> D1, g>=20 -> D2  (320 = 20*16).

#define BB 4096
#define NPRED 106
#define RR 53
#define OO 1024
#define DELTA_C 0.01f

#define KEXP 384
#define TM 128
#define TN 64
#define KC 128            // K per smem chunk
#define NCHUNKS 3
#define ROWB 272          // padded smem row: 128 bf16 = 256B + 16B pad (17x16B)

__device__ __nv_bfloat16 g_G[BB * KEXP];   // [b][k]
__device__ __nv_bfloat16 g_H[OO * KEXP];   // [o][k]
__device__ float g_s[BB];                  // DELTA * max_r max|x|
__device__ float g_T[OO];                  // max_r |w[r,o]|

__device__ __forceinline__ uint32_t smem_to_u32(const void* p) {
    uint32_t a;
    asm("{ .reg .u64 t; cvta.to.shared.u64 t, %1; cvt.u32.u64 %0, t; }"
        : "=r"(a) : "l"(p));
    return a;
}
__device__ __forceinline__ float lg2f(float v) {
    float r; asm("lg2.approx.f32 %0, %1;" : "=f"(r) : "f"(v)); return r;
}
__device__ __forceinline__ float ex2f(float v) {
    float r; asm("ex2.approx.f32 %0, %1;" : "=f"(r) : "f"(v)); return r;
}
__device__ __forceinline__ float pow32f(float v) {
    v = v * v; v = v * v; v = v * v; v = v * v; return v * v;
}
__device__ __forceinline__ void bsplit(float v, __nv_bfloat16& hi, __nv_bfloat16& lo) {
    hi = __float2bfloat16(v);
    lo = __float2bfloat16(v - __bfloat162float(hi));
}

#define LDSM_X4(r0, r1, r2, r3, addr) \
    asm volatile("ldmatrix.sync.aligned.m8n8.x4.shared.b16 {%0,%1,%2,%3}, [%4];" \
                 : "=r"(r0), "=r"(r1), "=r"(r2), "=r"(r3) : "r"(addr))

#define MMA_BF16(d, a0, a1, a2, a3, b0, b1) \
    asm volatile("mma.sync.aligned.m16n8k16.row.col.f32.bf16.bf16.f32 " \
                 "{%0,%1,%2,%3}, {%4,%5,%6,%7}, {%8,%9}, {%0,%1,%2,%3};" \
                 : "+f"((d)[0]), "+f"((d)[1]), "+f"((d)[2]), "+f"((d)[3]) \
                 : "r"(a0), "r"(a1), "r"(a2), "r"(a3), "r"(b0), "r"(b1))

// ---------------- Kernel 1: batch-side prep -> g_G, g_s ----------------
#define ROWS_PB 128
#define XPAD 107
__global__ void __launch_bounds__(128) k_rows(const float* __restrict__ x) {
    extern __shared__ float dsm[];
    float* s_x = dsm;                                             // [128][107]
    __nv_bfloat16* s_g = (__nv_bfloat16*)(dsm + ROWS_PB * XPAD);  // [128][384]

    int tid = threadIdx.x;
    int b0 = blockIdx.x * ROWS_PB;

    for (int i = tid; i < ROWS_PB * NPRED; i += 128) {
        int row = i / NPRED, col = i % NPRED;
        s_x[row * XPAD + col] = x[(long)(b0 + row) * NPRED + col];
    }
    __syncthreads();

    {
        const float* xr = &s_x[tid * XPAD];
        __nv_bfloat16* sg = &s_g[tid * KEXP];
        float mx = 0.0f;
#pragma unroll 4
        for (int r = 0; r < RR; r++) {
            float x1 = xr[r];
            float x2 = xr[53 + r];
            float A = ((x1 >= -1.0f) ? x1 : 0.0f) + ((x2 >= -1.0f) ? x2 : 0.0f);
            float a1 = fabsf(x1), a2 = fabsf(x2);
            float nU = -DELTA_C * (a1 + a2);
            __nv_bfloat16 ah, al, uh, ul;
            bsplit(A, ah, al);
            bsplit(nU, uh, ul);
            sg[6 * r + 0] = ah; sg[6 * r + 1] = ah; sg[6 * r + 2] = al;
            sg[6 * r + 3] = uh; sg[6 * r + 4] = uh; sg[6 * r + 5] = ul;
            mx = fmaxf(mx, fmaxf(a1, a2));
        }
        sg[318] = __float2bfloat16(0.0f);
        sg[319] = __float2bfloat16(0.0f);
        float inv = (mx > 0.0f) ? (1.0f / mx) : 0.0f;
#pragma unroll 4
        for (int r = 0; r < RR; r++) {
            float dv = fmaxf(fabsf(xr[r]), fabsf(xr[53 + r]));
            sg[320 + r] = __float2bfloat16(pow32f(dv * inv));
        }
        for (int k = 373; k < KEXP; k++) sg[k] = __float2bfloat16(0.0f);
        g_s[b0 + tid] = DELTA_C * mx;
    }
    __syncthreads();

    const uint4* src = (const uint4*)s_g;
    uint4* dst = (uint4*)&g_G[(long)b0 * KEXP];
    for (int i = tid; i < ROWS_PB * KEXP / 8; i += 128) dst[i] = src[i];
}

// ---------------- Kernel 2: weight-side prep -> g_H, g_T ----------------
__global__ void __launch_bounds__(256) k_wprep(const float* __restrict__ w) {
    __shared__ float s_wcol[8][64];
    int wid = threadIdx.x >> 5;
    int lid = threadIdx.x & 31;
    int o = blockIdx.x * 8 + wid;

    float w1 = (lid < RR) ? w[lid * OO + o] : 0.0f;
    float w2 = (lid + 32 < RR) ? w[(lid + 32) * OO + o] : 0.0f;
    s_wcol[wid][lid] = w1;
    s_wcol[wid][lid + 32] = w2;
    float m = fmaxf(fabsf(w1), fabsf(w2));
#pragma unroll
    for (int d = 16; d > 0; d >>= 1)
        m = fmaxf(m, __shfl_xor_sync(0xFFFFFFFF, m, d));
    float tinv = (m > 0.0f) ? (1.0f / m) : 0.0f;
    if (lid == 0) g_T[o] = m;
    __syncwarp();

    for (int k = lid; k < KEXP; k += 32) {
        __nv_bfloat16 v = __float2bfloat16(0.0f);
        if (k < 318) {
            int r = k / 6;
            int rem = k - 6 * r;
            int j = rem / 3;
            int t = rem - 3 * j;
            float wv = s_wcol[wid][r];
            float base = (j == 0) ? wv : fabsf(wv);
            __nv_bfloat16 hi, lo;
            bsplit(base, hi, lo);
            v = (t == 1) ? lo : hi;          // t0:hi, t1:lo, t2:hi
        } else if (k >= 320 && k < 320 + RR) {
            int r = k - 320;
            v = __float2bfloat16(pow32f(fabsf(s_wcol[wid][r]) * tinv));
        }
        g_H[(long)o * KEXP + k] = v;
    }
}

// ---------------- Kernel 3: mma.sync main ----------------
// grid (OO/TN, BB/TM) = (16, 32), 256 threads = 8 warps.
// Warp grid 4(M) x 2(N); warp tile 32x32; mma m16n8k16: 2(M) x 4(N) frags.
// smem: A [128][136 bf16] (272B rows), B [64][136], sT[64] f32, sS[128] f32.
#define SMEM_A 0
#define SMEM_B (TM * ROWB)                 // 34816
#define SMEM_T (SMEM_B + TN * ROWB)        // 52224
#define SMEM_S (SMEM_T + TN * 4)           // 52480
#define SMEM_TOTAL (SMEM_S + TM * 4)       // 52992

__global__ void __launch_bounds__(256) k_main(float* __restrict__ out) {
    extern __shared__ char smem[];
    uint32_t su = smem_to_u32(smem);
    int tid = threadIdx.x;
    int wid = tid >> 5;
    int lid = tid & 31;
    int o0 = blockIdx.x * TN;
    int b0 = blockIdx.y * TM;

    int warp_m = wid & 3;       // 4 x 32 rows
    int warp_n = wid >> 2;      // 2 x 32 cols
    int ro = warp_m * 32;
    int co = warp_n * 32;

    float* sT = (float*)(smem + SMEM_T);
    float* sS = (float*)(smem + SMEM_S);
    if (tid < TN) sT[tid] = g_T[o0 + tid];
    if (tid < TM) sS[tid] = g_s[b0 + tid];

    float acc1[2][4][4];   // sum path
    float acc2[2][4][4];   // p-norm path
#pragma unroll
    for (int mt = 0; mt < 2; mt++)
#pragma unroll
        for (int nt = 0; nt < 4; nt++)
#pragma unroll
            for (int j = 0; j < 4; j++) { acc1[mt][nt][j] = 0.0f; acc2[mt][nt][j] = 0.0f; }

    // per-lane ldmatrix address components
    int mat = lid >> 3, mr = lid & 7;
    // A x4 matrix order: (rows0-7,k0),(rows8-15,k0),(rows0-7,k0+8),(rows8-15,k0+8)
    int a_row_in16 = (mat & 1) * 8 + mr;
    int a_koff = (mat >> 1) * 16;           // bytes
    // B x4 matrix order: (n0-7,k0),(n0-7,k0+8),(n8-15,k0),(n8-15,k0+8)
    int b_row_in16 = (mat >> 1) * 8 + mr;
    int b_koff = (mat & 1) * 16;

#pragma unroll
    for (int c = 0; c < NCHUNKS; c++) {
        __syncthreads();
        // stage A chunk: 128 rows x 16 uint4 of data (17th segment = pad)
        for (int i = tid; i < TM * 16; i += 256) {
            int row = i >> 4, seg = i & 15;
            ((uint4*)(smem + SMEM_A))[row * 17 + seg] =
                *(const uint4*)&g_G[(long)(b0 + row) * KEXP + c * KC + seg * 8];
        }
        // stage B chunk: 64 rows x 16 uint4
        for (int i = tid; i < TN * 16; i += 256) {
            int row = i >> 4, seg = i & 15;
            ((uint4*)(smem + SMEM_B))[row * 17 + seg] =
                *(const uint4*)&g_H[(long)(o0 + row) * KEXP + c * KC + seg * 8];
        }
        __syncthreads();

#pragma unroll
        for (int ks = 0; ks < 8; ks++) {
            const int g = c * 8 + ks;             // compile-time
            uint32_t a[2][4], q[2][4];
#pragma unroll
            for (int mt = 0; mt < 2; mt++) {
                uint32_t addr = su + SMEM_A
                    + (uint32_t)(ro + mt * 16 + a_row_in16) * ROWB
                    + (uint32_t)(ks * 32 + a_koff);
                LDSM_X4(a[mt][0], a[mt][1], a[mt][2], a[mt][3], addr);
            }
#pragma unroll
            for (int bt = 0; bt < 2; bt++) {
                uint32_t addr = su + SMEM_B
                    + (uint32_t)(co + bt * 16 + b_row_in16) * ROWB
                    + (uint32_t)(ks * 32 + b_koff);
                LDSM_X4(q[bt][0], q[bt][1], q[bt][2], q[bt][3], addr);
            }
#pragma unroll
            for (int mt = 0; mt < 2; mt++) {
#pragma unroll
                for (int nt = 0; nt < 4; nt++) {
                    uint32_t bb0 = q[nt >> 1][(nt & 1) * 2];
                    uint32_t bb1 = q[nt >> 1][(nt & 1) * 2 + 1];
                    if (g < 20)
                        MMA_BF16(acc1[mt][nt], a[mt][0], a[mt][1], a[mt][2], a[mt][3], bb0, bb1);
                    else
                        MMA_BF16(acc2[mt][nt], a[mt][0], a[mt][1], a[mt][2], a[mt][3], bb0, bb1);
                }
            }
        }
    }

    // Epilogue: out = acc1 + s_b * t_o * acc2^(1/32)
    int qrow = lid >> 2;
    int qcol = (lid & 3) * 2;
#pragma unroll
    for (int mt = 0; mt < 2; mt++) {
#pragma unroll
        for (int nt = 0; nt < 4; nt++) {
            int r0 = ro + mt * 16 + qrow;
            int c0 = co + nt * 8 + qcol;
            float t0 = sT[c0], t1 = sT[c0 + 1];
            float s0 = sS[r0], s1 = sS[r0 + 8];
            float2 v;
            v.x = acc1[mt][nt][0] + s0 * t0 * ex2f(lg2f(acc2[mt][nt][0]) * 0.03125f);
            v.y = acc1[mt][nt][1] + s0 * t1 * ex2f(lg2f(acc2[mt][nt][1]) * 0.03125f);
            *(float2*)&out[(long)(b0 + r0) * OO + o0 + c0] = v;
            float2 u;
            u.x = acc1[mt][nt][2] + s1 * t0 * ex2f(lg2f(acc2[mt][nt][2]) * 0.03125f);
            u.y = acc1[mt][nt][3] + s1 * t1 * ex2f(lg2f(acc2[mt][nt][3]) * 0.03125f);
            *(float2*)&out[(long)(b0 + r0 + 8) * OO + o0 + c0] = u;
        }
    }
}

extern "C" void kernel_launch(void* const* d_in, const int* in_sizes, int n_in,
                              void* d_out, int out_size) {
    const float* x = (const float*)d_in[0];   // [4096, 106] f32
    const float* w = (const float*)d_in[1];   // [54, 1024] f32 (row 53 unused)
    float* out = (float*)d_out;               // [4096, 1024] f32

    const int rows_smem = ROWS_PB * XPAD * 4 + ROWS_PB * KEXP * 2;  // 153088
    cudaFuncSetAttribute(k_rows, cudaFuncAttributeMaxDynamicSharedMemorySize, rows_smem);
    cudaFuncSetAttribute(k_main, cudaFuncAttributeMaxDynamicSharedMemorySize, SMEM_TOTAL);

    k_rows<<<BB / ROWS_PB, 128, rows_smem>>>(x);
    k_wprep<<<OO / 8, 256>>>(w);
    dim3 grid(OO / TN, BB / TM);   // (16, 32)
    k_main<<<grid, 256, SMEM_TOTAL>>>(out);
}

// round 15
// speedup vs baseline: 1.7179x; 1.6656x over previous
#include <cuda_runtime.h>
#include <cuda_bf16.h>
#include <cstdint>

// HGT_DNF conjunction layer via portable tensor-core MMA (mma.sync bf16).
// idx structure: pairs {r, 53+r}, weight row 53 unused. RR=53.
//   out[b,o] = sum_r( A*w - dU*|w| ) + max_r( dV*|w| )
// max via p-norm P=32:  s_b * t_o * ( sum_r Vp*awp )^(1/32)
// Two GEMMs over expanded K=384 (6x64 bf16):
//   k in [0,318): split-bf16 sum path (hi*hi + hi*lo + lo*hi) -> D1
//   k in [320,373): p-norm path (single bf16)                 -> D2

#define BB 4096
#define NPRED 106
#define RR 53
#define OO 1024
#define DELTA_C 0.01f

#define KEXP 384
#define TM 128
#define TN 64
#define KC 128            // K per smem chunk
#define NCHUNKS 3
#define ROWB 272          // padded smem row: 128 bf16 = 256B + 16B pad

__device__ __nv_bfloat16 g_G[BB * KEXP];   // [b][k]
__device__ __nv_bfloat16 g_H[OO * KEXP];   // [o][k]
__device__ float g_s[BB];                  // DELTA * max_r max|x|
__device__ float g_T[OO];                  // max_r |w[r,o]|

__device__ __forceinline__ uint32_t smem_to_u32(const void* p) {
    uint32_t a;
    asm("{ .reg .u64 t; cvta.to.shared.u64 t, %1; cvt.u32.u64 %0, t; }"
        : "=r"(a) : "l"(p));
    return a;
}
__device__ __forceinline__ float lg2f(float v) {
    float r; asm("lg2.approx.f32 %0, %1;" : "=f"(r) : "f"(v)); return r;
}
__device__ __forceinline__ float ex2f(float v) {
    float r; asm("ex2.approx.f32 %0, %1;" : "=f"(r) : "f"(v)); return r;
}
__device__ __forceinline__ float pow32f(float v) {
    v = v * v; v = v * v; v = v * v; v = v * v; return v * v;
}
__device__ __forceinline__ void bsplit(float v, __nv_bfloat16& hi, __nv_bfloat16& lo) {
    hi = __float2bfloat16(v);
    lo = __float2bfloat16(v - __bfloat162float(hi));
}

#define LDSM_X4(r0, r1, r2, r3, addr) \
    asm volatile("ldmatrix.sync.aligned.m8n8.x4.shared.b16 {%0,%1,%2,%3}, [%4];" \
                 : "=r"(r0), "=r"(r1), "=r"(r2), "=r"(r3) : "r"(addr))

#define MMA_BF16(d, a0, a1, a2, a3, b0, b1) \
    asm volatile("mma.sync.aligned.m16n8k16.row.col.f32.bf16.bf16.f32 " \
                 "{%0,%1,%2,%3}, {%4,%5,%6,%7}, {%8,%9}, {%0,%1,%2,%3};" \
                 : "+f"((d)[0]), "+f"((d)[1]), "+f"((d)[2]), "+f"((d)[3]) \
                 : "r"(a0), "r"(a1), "r"(a2), "r"(a3), "r"(b0), "r"(b1))

// ---------------- Kernel 1: batch-side prep (warp-per-row) ----------------
// 8 warps per block, one batch row per warp, grid = BB/8 = 512 CTAs.
#define KR_WARPS 8
__global__ void __launch_bounds__(KR_WARPS * 32) k_rows(const float* __restrict__ x) {
    __shared__ float sx[KR_WARPS][112];
    __shared__ __nv_bfloat16 sg[KR_WARPS][KEXP];

    int wid = threadIdx.x >> 5;
    int lid = threadIdx.x & 31;
    int b = blockIdx.x * KR_WARPS + wid;

    // cooperative row load (106 floats): lanes read strided, coalesced
    const float* xrow = &x[(long)b * NPRED];
#pragma unroll
    for (int s = 0; s < 4; s++) {
        int i = s * 32 + lid;
        if (i < NPRED) sx[wid][i] = xrow[i];
    }
    __syncwarp();

    const float* xr = sx[wid];
    __nv_bfloat16* g = sg[wid];

    // lane l handles r=l (all 32 valid) and r=32+l (valid l<21)
    float dv1 = 0.0f, dv2 = 0.0f;
    float A1 = 0.0f, nU1 = 0.0f, A2 = 0.0f, nU2 = 0.0f;
    {
        int r = lid;
        float x1 = xr[r], x2 = xr[53 + r];
        A1 = ((x1 >= -1.0f) ? x1 : 0.0f) + ((x2 >= -1.0f) ? x2 : 0.0f);
        float a1 = fabsf(x1), a2 = fabsf(x2);
        nU1 = -DELTA_C * (a1 + a2);
        dv1 = fmaxf(a1, a2);
    }
    if (lid < 21) {
        int r = 32 + lid;
        float x1 = xr[r], x2 = xr[53 + r];
        A2 = ((x1 >= -1.0f) ? x1 : 0.0f) + ((x2 >= -1.0f) ? x2 : 0.0f);
        float a1 = fabsf(x1), a2 = fabsf(x2);
        nU2 = -DELTA_C * (a1 + a2);
        dv2 = fmaxf(a1, a2);
    }

    // warp max over all dv
    float mx = fmaxf(dv1, dv2);
#pragma unroll
    for (int d = 16; d > 0; d >>= 1)
        mx = fmaxf(mx, __shfl_xor_sync(0xFFFFFFFF, mx, d));
    float inv = (mx > 0.0f) ? (1.0f / mx) : 0.0f;

    // write slots
    {
        int r = lid;
        __nv_bfloat16 ah, al, uh, ul;
        bsplit(A1, ah, al);
        bsplit(nU1, uh, ul);
        g[6 * r + 0] = ah; g[6 * r + 1] = ah; g[6 * r + 2] = al;
        g[6 * r + 3] = uh; g[6 * r + 4] = uh; g[6 * r + 5] = ul;
        g[320 + r] = __float2bfloat16(pow32f(dv1 * inv));
    }
    if (lid < 21) {
        int r = 32 + lid;
        __nv_bfloat16 ah, al, uh, ul;
        bsplit(A2, ah, al);
        bsplit(nU2, uh, ul);
        g[6 * r + 0] = ah; g[6 * r + 1] = ah; g[6 * r + 2] = al;
        g[6 * r + 3] = uh; g[6 * r + 4] = uh; g[6 * r + 5] = ul;
        g[320 + r] = __float2bfloat16(pow32f(dv2 * inv));
    }
    // zero padding slots: 318,319 and 373..383 (13 slots)
    if (lid < 13) {
        int k = (lid < 2) ? (318 + lid) : (371 + lid);   // 318,319,373..383
        g[k] = __float2bfloat16(0.0f);
    }
    if (lid == 0) g_s[b] = DELTA_C * mx;
    __syncwarp();

    // coalesced writeback: 384 bf16 = 48 uint4 per row
    const uint4* src = (const uint4*)g;
    uint4* dst = (uint4*)&g_G[(long)b * KEXP];
    dst[lid] = src[lid];
    if (lid < 16) dst[32 + lid] = src[32 + lid];
}

// ---------------- Kernel 2: weight-side prep -> g_H, g_T ----------------
__global__ void __launch_bounds__(256) k_wprep(const float* __restrict__ w) {
    __shared__ float s_wcol[8][64];
    int wid = threadIdx.x >> 5;
    int lid = threadIdx.x & 31;
    int o = blockIdx.x * 8 + wid;

    float w1 = (lid < RR) ? w[lid * OO + o] : 0.0f;
    float w2 = (lid + 32 < RR) ? w[(lid + 32) * OO + o] : 0.0f;
    s_wcol[wid][lid] = w1;
    s_wcol[wid][lid + 32] = w2;
    float m = fmaxf(fabsf(w1), fabsf(w2));
#pragma unroll
    for (int d = 16; d > 0; d >>= 1)
        m = fmaxf(m, __shfl_xor_sync(0xFFFFFFFF, m, d));
    float tinv = (m > 0.0f) ? (1.0f / m) : 0.0f;
    if (lid == 0) g_T[o] = m;
    __syncwarp();

    for (int k = lid; k < KEXP; k += 32) {
        __nv_bfloat16 v = __float2bfloat16(0.0f);
        if (k < 318) {
            int r = k / 6;
            int rem = k - 6 * r;
            int j = rem / 3;
            int t = rem - 3 * j;
            float wv = s_wcol[wid][r];
            float base = (j == 0) ? wv : fabsf(wv);
            __nv_bfloat16 hi, lo;
            bsplit(base, hi, lo);
            v = (t == 1) ? lo : hi;          // t0:hi, t1:lo, t2:hi
        } else if (k >= 320 && k < 320 + RR) {
            int r = k - 320;
            v = __float2bfloat16(pow32f(fabsf(s_wcol[wid][r]) * tinv));
        }
        g_H[(long)o * KEXP + k] = v;
    }
}

// ---------------- Kernel 3: mma.sync main ----------------
// grid (OO/TN, BB/TM) = (16, 32), 256 threads = 8 warps.
// Warp grid 4(M) x 2(N); warp tile 32x32; mma m16n8k16: 2(M) x 4(N) frags.
#define SMEM_A 0
#define SMEM_B (TM * ROWB)                 // 34816
#define SMEM_T (SMEM_B + TN * ROWB)        // 52224
#define SMEM_S (SMEM_T + TN * 4)           // 52480
#define SMEM_TOTAL (SMEM_S + TM * 4)       // 52992

__global__ void __launch_bounds__(256) k_main(float* __restrict__ out) {
    extern __shared__ char smem[];
    uint32_t su = smem_to_u32(smem);
    int tid = threadIdx.x;
    int wid = tid >> 5;
    int lid = tid & 31;
    int o0 = blockIdx.x * TN;
    int b0 = blockIdx.y * TM;

    int warp_m = wid & 3;
    int warp_n = wid >> 2;
    int ro = warp_m * 32;
    int co = warp_n * 32;

    float* sT = (float*)(smem + SMEM_T);
    float* sS = (float*)(smem + SMEM_S);
    if (tid < TN) sT[tid] = g_T[o0 + tid];
    if (tid < TM) sS[tid] = g_s[b0 + tid];

    float acc1[2][4][4];
    float acc2[2][4][4];
#pragma unroll
    for (int mt = 0; mt < 2; mt++)
#pragma unroll
        for (int nt = 0; nt < 4; nt++)
#pragma unroll
            for (int j = 0; j < 4; j++) { acc1[mt][nt][j] = 0.0f; acc2[mt][nt][j] = 0.0f; }

    int mat = lid >> 3, mr = lid & 7;
    int a_row_in16 = (mat & 1) * 8 + mr;
    int a_koff = (mat >> 1) * 16;
    int b_row_in16 = (mat >> 1) * 8 + mr;
    int b_koff = (mat & 1) * 16;

#pragma unroll
    for (int c = 0; c < NCHUNKS; c++) {
        __syncthreads();
        for (int i = tid; i < TM * 16; i += 256) {
            int row = i >> 4, seg = i & 15;
            ((uint4*)(smem + SMEM_A))[row * 17 + seg] =
                *(const uint4*)&g_G[(long)(b0 + row) * KEXP + c * KC + seg * 8];
        }
        for (int i = tid; i < TN * 16; i += 256) {
            int row = i >> 4, seg = i & 15;
            ((uint4*)(smem + SMEM_B))[row * 17 + seg] =
                *(const uint4*)&g_H[(long)(o0 + row) * KEXP + c * KC + seg * 8];
        }
        __syncthreads();

#pragma unroll
        for (int ks = 0; ks < 8; ks++) {
            const int g = c * 8 + ks;
            uint32_t a[2][4], q[2][4];
#pragma unroll
            for (int mt = 0; mt < 2; mt++) {
                uint32_t addr = su + SMEM_A
                    + (uint32_t)(ro + mt * 16 + a_row_in16) * ROWB
                    + (uint32_t)(ks * 32 + a_koff);
                LDSM_X4(a[mt][0], a[mt][1], a[mt][2], a[mt][3], addr);
            }
#pragma unroll
            for (int bt = 0; bt < 2; bt++) {
                uint32_t addr = su + SMEM_B
                    + (uint32_t)(co + bt * 16 + b_row_in16) * ROWB
                    + (uint32_t)(ks * 32 + b_koff);
                LDSM_X4(q[bt][0], q[bt][1], q[bt][2], q[bt][3], addr);
            }
#pragma unroll
            for (int mt = 0; mt < 2; mt++) {
#pragma unroll
                for (int nt = 0; nt < 4; nt++) {
                    uint32_t bb0 = q[nt >> 1][(nt & 1) * 2];
                    uint32_t bb1 = q[nt >> 1][(nt & 1) * 2 + 1];
                    if (g < 20)
                        MMA_BF16(acc1[mt][nt], a[mt][0], a[mt][1], a[mt][2], a[mt][3], bb0, bb1);
                    else
                        MMA_BF16(acc2[mt][nt], a[mt][0], a[mt][1], a[mt][2], a[mt][3], bb0, bb1);
                }
            }
        }
    }

    int qrow = lid >> 2;
    int qcol = (lid & 3) * 2;
#pragma unroll
    for (int mt = 0; mt < 2; mt++) {
#pragma unroll
        for (int nt = 0; nt < 4; nt++) {
            int r0 = ro + mt * 16 + qrow;
            int c0 = co + nt * 8 + qcol;
            float t0 = sT[c0], t1 = sT[c0 + 1];
            float s0 = sS[r0], s1 = sS[r0 + 8];
            float2 v;
            v.x = acc1[mt][nt][0] + s0 * t0 * ex2f(lg2f(acc2[mt][nt][0]) * 0.03125f);
            v.y = acc1[mt][nt][1] + s0 * t1 * ex2f(lg2f(acc2[mt][nt][1]) * 0.03125f);
            *(float2*)&out[(long)(b0 + r0) * OO + o0 + c0] = v;
            float2 u;
            u.x = acc1[mt][nt][2] + s1 * t0 * ex2f(lg2f(acc2[mt][nt][2]) * 0.03125f);
            u.y = acc1[mt][nt][3] + s1 * t1 * ex2f(lg2f(acc2[mt][nt][3]) * 0.03125f);
            *(float2*)&out[(long)(b0 + r0 + 8) * OO + o0 + c0] = u;
        }
    }
}

extern "C" void kernel_launch(void* const* d_in, const int* in_sizes, int n_in,
                              void* d_out, int out_size) {
    const float* x = (const float*)d_in[0];   // [4096, 106] f32
    const float* w = (const float*)d_in[1];   // [54, 1024] f32 (row 53 unused)
    float* out = (float*)d_out;               // [4096, 1024] f32

    cudaFuncSetAttribute(k_main, cudaFuncAttributeMaxDynamicSharedMemorySize, SMEM_TOTAL);

    k_rows<<<BB / KR_WARPS, KR_WARPS * 32>>>(x);
    k_wprep<<<OO / 8, 256>>>(w);
    dim3 grid(OO / TN, BB / TM);   // (16, 32)
    k_main<<<grid, 256, SMEM_TOTAL>>>(out);
}

// round 17
// speedup vs baseline: 1.9591x; 1.1404x over previous
#include <cuda_runtime.h>
#include <cuda_bf16.h>
#include <cuda_fp16.h>
#include <cstdint>

// HGT_DNF conjunction layer via portable tensor-core MMA (mma.sync).
// idx structure: pairs {r, 53+r}, weight row 53 unused. RR=53.
//   out[b,o] = sum_r( A*w - dU*|w| ) + max_r( dV*|w| )
// max via p-norm P=32:  s_b * t_o * ( sum_r Vp*awp )^(1/32)
// K layout (224 = 14 k16-steps):
//   k = 3r+t, r<53 (fp16):   t0: ah*wh   t1: al*wh   t2: nU_h*|w|_h
//     (A = ah+al exact fp16 split; error = A*(w-wh) ~ 2^-12 rel;
//      dU term is DELTA-scaled -> single fp16 slot suffices)
//   k = 159: zero pad
//   k = 160+r, r<53 (bf16):  Vp * awp   (p-norm path)
//   k = 213..223: zero pad
// Steps g<10: fp16 MMA -> acc1 (sum). Steps g>=10: bf16 MMA -> acc2 (p-norm).

#define BB 4096
#define NPRED 106
#define RR 53
#define OO 1024
#define DELTA_C 0.01f

#define KEXP 224
#define TM 128
#define TN 64
#define KC 112            // K per smem chunk (7 k16-steps)
#define NCHUNKS 2
#define ROWB 240          // smem row: 112 bf16 = 224B data + 16B pad (15x16B)

__device__ unsigned short g_G[BB * KEXP];  // [b][k] raw 16-bit (fp16/bf16 regions)
__device__ unsigned short g_H[OO * KEXP];  // [o][k]
__device__ float g_s[BB];                  // DELTA * max_r max|x|
__device__ float g_T[OO];                  // max_r |w[r,o]|

__device__ __forceinline__ uint32_t smem_to_u32(const void* p) {
    uint32_t a;
    asm("{ .reg .u64 t; cvta.to.shared.u64 t, %1; cvt.u32.u64 %0, t; }"
        : "=r"(a) : "l"(p));
    return a;
}
__device__ __forceinline__ float lg2f(float v) {
    float r; asm("lg2.approx.f32 %0, %1;" : "=f"(r) : "f"(v)); return r;
}
__device__ __forceinline__ float ex2f(float v) {
    float r; asm("ex2.approx.f32 %0, %1;" : "=f"(r) : "f"(v)); return r;
}
__device__ __forceinline__ float pow32f(float v) {
    v = v * v; v = v * v; v = v * v; v = v * v; return v * v;
}
__device__ __forceinline__ unsigned short h_bits(__half h) {
    return __half_as_ushort(h);
}
__device__ __forceinline__ unsigned short b_bits(__nv_bfloat16 b) {
    return *reinterpret_cast<unsigned short*>(&b);
}

#define LDSM_X4(r0, r1, r2, r3, addr) \
    asm volatile("ldmatrix.sync.aligned.m8n8.x4.shared.b16 {%0,%1,%2,%3}, [%4];" \
                 : "=r"(r0), "=r"(r1), "=r"(r2), "=r"(r3) : "r"(addr))

#define MMA_BF16(d, a0, a1, a2, a3, b0, b1) \
    asm volatile("mma.sync.aligned.m16n8k16.row.col.f32.bf16.bf16.f32 " \
                 "{%0,%1,%2,%3}, {%4,%5,%6,%7}, {%8,%9}, {%0,%1,%2,%3};" \
                 : "+f"((d)[0]), "+f"((d)[1]), "+f"((d)[2]), "+f"((d)[3]) \
                 : "r"(a0), "r"(a1), "r"(a2), "r"(a3), "r"(b0), "r"(b1))

#define MMA_F16(d, a0, a1, a2, a3, b0, b1) \
    asm volatile("mma.sync.aligned.m16n8k16.row.col.f32.f16.f16.f32 " \
                 "{%0,%1,%2,%3}, {%4,%5,%6,%7}, {%8,%9}, {%0,%1,%2,%3};" \
                 : "+f"((d)[0]), "+f"((d)[1]), "+f"((d)[2]), "+f"((d)[3]) \
                 : "r"(a0), "r"(a1), "r"(a2), "r"(a3), "r"(b0), "r"(b1))

// ---------------- Kernel 1: fused prep (batch rows + weight cols) ----------
// blocks [0, 512): warp-per-batch-row (8 rows/block)
// blocks [512, 640): warp-per-out-col (8 cols/block)
#define KR_WARPS 8
#define ROW_BLOCKS (BB / KR_WARPS)     // 512
#define COL_BLOCKS (OO / 8)            // 128

__global__ void __launch_bounds__(256) k_prep(const float* __restrict__ x,
                                              const float* __restrict__ w) {
    __shared__ float sx[KR_WARPS][112];
    __shared__ unsigned short sg[KR_WARPS][KEXP];
    __shared__ float s_wcol[8][64];

    int wid = threadIdx.x >> 5;
    int lid = threadIdx.x & 31;

    if (blockIdx.x < ROW_BLOCKS) {
        // ---- batch-row part ----
        int b = blockIdx.x * KR_WARPS + wid;
        const float* xrow = &x[(long)b * NPRED];
#pragma unroll
        for (int s = 0; s < 4; s++) {
            int i = s * 32 + lid;
            if (i < NPRED) sx[wid][i] = xrow[i];
        }
        __syncwarp();

        const float* xr = sx[wid];
        unsigned short* g = sg[wid];

        float dv1 = 0.0f, dv2 = 0.0f;
        float A1 = 0.0f, nU1 = 0.0f, A2 = 0.0f, nU2 = 0.0f;
        {
            float x1 = xr[lid], x2 = xr[53 + lid];
            A1 = ((x1 >= -1.0f) ? x1 : 0.0f) + ((x2 >= -1.0f) ? x2 : 0.0f);
            float a1 = fabsf(x1), a2 = fabsf(x2);
            nU1 = -DELTA_C * (a1 + a2);
            dv1 = fmaxf(a1, a2);
        }
        if (lid < 21) {
            float x1 = xr[32 + lid], x2 = xr[85 + lid];
            A2 = ((x1 >= -1.0f) ? x1 : 0.0f) + ((x2 >= -1.0f) ? x2 : 0.0f);
            float a1 = fabsf(x1), a2 = fabsf(x2);
            nU2 = -DELTA_C * (a1 + a2);
            dv2 = fmaxf(a1, a2);
        }
        float mx = fmaxf(dv1, dv2);
#pragma unroll
        for (int d = 16; d > 0; d >>= 1)
            mx = fmaxf(mx, __shfl_xor_sync(0xFFFFFFFF, mx, d));
        float inv = (mx > 0.0f) ? (1.0f / mx) : 0.0f;

        {
            int r = lid;
            __half ah = __float2half_rn(A1);
            __half al = __float2half_rn(A1 - __half2float(ah));
            g[3 * r + 0] = h_bits(ah);
            g[3 * r + 1] = h_bits(al);
            g[3 * r + 2] = h_bits(__float2half_rn(nU1));
            g[160 + r] = b_bits(__float2bfloat16(pow32f(dv1 * inv)));
        }
        if (lid < 21) {
            int r = 32 + lid;
            __half ah = __float2half_rn(A2);
            __half al = __float2half_rn(A2 - __half2float(ah));
            g[3 * r + 0] = h_bits(ah);
            g[3 * r + 1] = h_bits(al);
            g[3 * r + 2] = h_bits(__float2half_rn(nU2));
            g[160 + r] = b_bits(__float2bfloat16(pow32f(dv2 * inv)));
        }
        // zero pads: slot 159 and slots 213..223 (12 total)
        if (lid < 12) {
            int k = (lid == 0) ? 159 : (212 + lid);
            g[k] = 0;
        }
        if (lid == 0) g_s[b] = DELTA_C * mx;
        __syncwarp();

        // writeback: 224 u16 = 448 B = 28 uint4
        const uint4* src = (const uint4*)g;
        uint4* dst = (uint4*)&g_G[(long)b * KEXP];
        if (lid < 28) dst[lid] = src[lid];
    } else {
        // ---- weight-col part ----
        int o = (blockIdx.x - ROW_BLOCKS) * 8 + wid;
        float w1 = (lid < RR) ? w[lid * OO + o] : 0.0f;
        float w2 = (lid + 32 < RR) ? w[(lid + 32) * OO + o] : 0.0f;
        s_wcol[wid][lid] = w1;
        s_wcol[wid][lid + 32] = w2;
        float m = fmaxf(fabsf(w1), fabsf(w2));
#pragma unroll
        for (int d = 16; d > 0; d >>= 1)
            m = fmaxf(m, __shfl_xor_sync(0xFFFFFFFF, m, d));
        float tinv = (m > 0.0f) ? (1.0f / m) : 0.0f;
        if (lid == 0) g_T[o] = m;
        __syncwarp();

        for (int k = lid; k < KEXP; k += 32) {
            unsigned short v = 0;
            if (k < 159) {
                int r = k / 3;
                int t = k - 3 * r;
                float wv = s_wcol[wid][r];
                v = h_bits(__float2half_rn((t < 2) ? wv : fabsf(wv)));
            } else if (k >= 160 && k < 160 + RR) {
                int r = k - 160;
                v = b_bits(__float2bfloat16(pow32f(fabsf(s_wcol[wid][r]) * tinv)));
            }
            g_H[(long)o * KEXP + k] = v;
        }
    }
}

// ---------------- Kernel 2: mma.sync main ----------------
// grid (OO/TN, BB/TM) = (16, 32), 256 threads = 8 warps.
// Warp grid 4(M) x 2(N); warp tile 32x32; mma m16n8k16: 2(M) x 4(N) frags.
#define SMEM_A 0
#define SMEM_B (TM * ROWB)                 // 30720
#define SMEM_T (SMEM_B + TN * ROWB)        // 46080
#define SMEM_S (SMEM_T + TN * 4)           // 46336
#define SMEM_TOTAL (SMEM_S + TM * 4)       // 46848

__global__ void __launch_bounds__(256) k_main(float* __restrict__ out) {
    extern __shared__ char smem[];
    uint32_t su = smem_to_u32(smem);
    int tid = threadIdx.x;
    int wid = tid >> 5;
    int lid = tid & 31;
    int o0 = blockIdx.x * TN;
    int b0 = blockIdx.y * TM;

    int warp_m = wid & 3;
    int warp_n = wid >> 2;
    int ro = warp_m * 32;
    int co = warp_n * 32;

    float* sT = (float*)(smem + SMEM_T);
    float* sS = (float*)(smem + SMEM_S);
    if (tid < TN) sT[tid] = g_T[o0 + tid];
    if (tid < TM) sS[tid] = g_s[b0 + tid];

    float acc1[2][4][4];
    float acc2[2][4][4];
#pragma unroll
    for (int mt = 0; mt < 2; mt++)
#pragma unroll
        for (int nt = 0; nt < 4; nt++)
#pragma unroll
            for (int j = 0; j < 4; j++) { acc1[mt][nt][j] = 0.0f; acc2[mt][nt][j] = 0.0f; }

    int mat = lid >> 3, mr = lid & 7;
    int a_row_in16 = (mat & 1) * 8 + mr;
    int a_koff = (mat >> 1) * 16;
    int b_row_in16 = (mat >> 1) * 8 + mr;
    int b_koff = (mat & 1) * 16;

#pragma unroll
    for (int c = 0; c < NCHUNKS; c++) {
        __syncthreads();
        // stage A chunk: 128 rows x 14 uint4 (row stride 15 uint4, last = pad)
        for (int i = tid; i < TM * 14; i += 256) {
            int row = i / 14, seg = i - row * 14;
            ((uint4*)(smem + SMEM_A))[row * 15 + seg] =
                *(const uint4*)&g_G[(long)(b0 + row) * KEXP + c * KC + seg * 8];
        }
        // stage B chunk: 64 rows x 14 uint4
        for (int i = tid; i < TN * 14; i += 256) {
            int row = i / 14, seg = i - row * 14;
            ((uint4*)(smem + SMEM_B))[row * 15 + seg] =
                *(const uint4*)&g_H[(long)(o0 + row) * KEXP + c * KC + seg * 8];
        }
        __syncthreads();

#pragma unroll
        for (int ks = 0; ks < 7; ks++) {
            const int g = c * 7 + ks;          // 0..13
            uint32_t a[2][4], q[2][4];
#pragma unroll
            for (int mt = 0; mt < 2; mt++) {
                uint32_t addr = su + SMEM_A
                    + (uint32_t)(ro + mt * 16 + a_row_in16) * ROWB
                    + (uint32_t)(ks * 32 + a_koff);
                LDSM_X4(a[mt][0], a[mt][1], a[mt][2], a[mt][3], addr);
            }
#pragma unroll
            for (int bt = 0; bt < 2; bt++) {
                uint32_t addr = su + SMEM_B
                    + (uint32_t)(co + bt * 16 + b_row_in16) * ROWB
                    + (uint32_t)(ks * 32 + b_koff);
                LDSM_X4(q[bt][0], q[bt][1], q[bt][2], q[bt][3], addr);
            }
#pragma unroll
            for (int mt = 0; mt < 2; mt++) {
#pragma unroll
                for (int nt = 0; nt < 4; nt++) {
                    uint32_t bb0 = q[nt >> 1][(nt & 1) * 2];
                    uint32_t bb1 = q[nt >> 1][(nt & 1) * 2 + 1];
                    if (g < 10)
                        MMA_F16(acc1[mt][nt], a[mt][0], a[mt][1], a[mt][2], a[mt][3], bb0, bb1);
                    else
                        MMA_BF16(acc2[mt][nt], a[mt][0], a[mt][1], a[mt][2], a[mt][3], bb0, bb1);
                }
            }
        }
    }

    int qrow = lid >> 2;
    int qcol = (lid & 3) * 2;
#pragma unroll
    for (int mt = 0; mt < 2; mt++) {
#pragma unroll
        for (int nt = 0; nt < 4; nt++) {
            int r0 = ro + mt * 16 + qrow;
            int c0 = co + nt * 8 + qcol;
            float t0 = sT[c0], t1 = sT[c0 + 1];
            float s0 = sS[r0], s1 = sS[r0 + 8];
            float2 v;
            v.x = acc1[mt][nt][0] + s0 * t0 * ex2f(lg2f(acc2[mt][nt][0]) * 0.03125f);
            v.y = acc1[mt][nt][1] + s0 * t1 * ex2f(lg2f(acc2[mt][nt][1]) * 0.03125f);
            *(float2*)&out[(long)(b0 + r0) * OO + o0 + c0] = v;
            float2 u;
            u.x = acc1[mt][nt][2] + s1 * t0 * ex2f(lg2f(acc2[mt][nt][2]) * 0.03125f);
            u.y = acc1[mt][nt][3] + s1 * t1 * ex2f(lg2f(acc2[mt][nt][3]) * 0.03125f);
            *(float2*)&out[(long)(b0 + r0 + 8) * OO + o0 + c0] = u;
        }
    }
}

extern "C" void kernel_launch(void* const* d_in, const int* in_sizes, int n_in,
                              void* d_out, int out_size) {
    const float* x = (const float*)d_in[0];   // [4096, 106] f32
    const float* w = (const float*)d_in[1];   // [54, 1024] f32 (row 53 unused)
    float* out = (float*)d_out;               // [4096, 1024] f32

    cudaFuncSetAttribute(k_main, cudaFuncAttributeMaxDynamicSharedMemorySize, SMEM_TOTAL);

    k_prep<<<ROW_BLOCKS + COL_BLOCKS, 256>>>(x, w);
    dim3 grid(OO / TN, BB / TM);   // (16, 32)
    k_main<<<grid, 256, SMEM_TOTAL>>>(out);
}